// round 1
// baseline (speedup 1.0000x reference)
#include <cuda_runtime.h>
#include <cuda_bf16.h>
#include <math_constants.h>

// Shapes (fixed by the problem)
#define NB 4
#define TB 8
#define NT (NB*TB)        // 32 batches
#define CC 256            // channels (reduction dim for scores)
#define C2 256            // value channels
#define HW 1024           // p == q == H*W
#define PVAL_ELEMS ((size_t)NT * C2 * HW)         // 8,388,608
#define ATTN_ELEMS ((size_t)NT * HW * HW)         // 33,554,432

#define BM 64
#define BN 64
#define BK 16

// -------------------------------------------------------------------------
// Kernel 1: scores[p][q] = (1/16) * sum_c K[c][p] * Q[c][q]
// K, Q layout: [nt][c][p] (p contiguous). Output S: [nt][p][q] (q contiguous).
// -------------------------------------------------------------------------
__global__ __launch_bounds__(256) void scores_kernel(
    const float* __restrict__ K, const float* __restrict__ Q,
    float* __restrict__ S)
{
    const int nt    = blockIdx.z;
    const int pBase = blockIdx.y * BM;
    const int qBase = blockIdx.x * BN;

    const float* Kb = K + (size_t)nt * CC * HW;
    const float* Qb = Q + (size_t)nt * CC * HW;
    float*       Sb = S + (size_t)nt * HW * HW;

    __shared__ float As[BK][BM];   // [c][p]
    __shared__ float Bs[BK][BN];   // [c][q]

    const int tx = threadIdx.x;           // 0..15 (q)
    const int ty = threadIdx.y;           // 0..15 (p)
    const int tid = ty * 16 + tx;

    float acc[4][4];
    #pragma unroll
    for (int i = 0; i < 4; ++i)
        #pragma unroll
        for (int j = 0; j < 4; ++j) acc[i][j] = 0.f;

    const int lr  = tid / 16;        // row (c) 0..15
    const int lc4 = (tid % 16) * 4;  // col (p/q) in tile

    for (int k0 = 0; k0 < CC; k0 += BK) {
        float4 a = *reinterpret_cast<const float4*>(&Kb[(size_t)(k0 + lr) * HW + pBase + lc4]);
        float4 b = *reinterpret_cast<const float4*>(&Qb[(size_t)(k0 + lr) * HW + qBase + lc4]);
        *reinterpret_cast<float4*>(&As[lr][lc4]) = a;
        *reinterpret_cast<float4*>(&Bs[lr][lc4]) = b;
        __syncthreads();

        #pragma unroll
        for (int kk = 0; kk < BK; ++kk) {
            float av[4], bv[4];
            *reinterpret_cast<float4*>(av) = *reinterpret_cast<const float4*>(&As[kk][ty * 4]);
            *reinterpret_cast<float4*>(bv) = *reinterpret_cast<const float4*>(&Bs[kk][tx * 4]);
            #pragma unroll
            for (int i = 0; i < 4; ++i)
                #pragma unroll
                for (int j = 0; j < 4; ++j)
                    acc[i][j] = fmaf(av[i], bv[j], acc[i][j]);
        }
        __syncthreads();
    }

    const float scale = 1.0f / 16.0f;   // 1/sqrt(256)
    #pragma unroll
    for (int i = 0; i < 4; ++i) {
        const int p = pBase + ty * 4 + i;
        float4 v;
        v.x = acc[i][0] * scale;
        v.y = acc[i][1] * scale;
        v.z = acc[i][2] * scale;
        v.w = acc[i][3] * scale;
        *reinterpret_cast<float4*>(&Sb[(size_t)p * HW + qBase + tx * 4]) = v;
    }
}

// -------------------------------------------------------------------------
// Kernel 2: in-place softmax over the p axis (dim -2) of S [nt][p][q].
// Block handles 32 q-columns of one batch; 8 "row teams" (ty) stride over p.
// -------------------------------------------------------------------------
__global__ __launch_bounds__(256) void softmax_p_kernel(float* __restrict__ S)
{
    const int nt = blockIdx.y;
    const int tx = threadIdx.x;              // 0..31  -> q within tile
    const int ty = threadIdx.y;              // 0..7   -> p stripe
    const int q  = blockIdx.x * 32 + tx;

    float* col = S + (size_t)nt * HW * HW + q;

    // online (max, sum) over this thread's stripe
    float m = -CUDART_INF_F;
    float s = 0.f;
    for (int p = ty; p < HW; p += 8) {
        float x = col[(size_t)p * HW];
        float mn = fmaxf(m, x);
        s = s * __expf(m - mn) + __expf(x - mn);
        m = mn;
    }

    __shared__ float sm[8][32];
    __shared__ float ss[8][32];
    sm[ty][tx] = m;
    ss[ty][tx] = s;
    __syncthreads();

    if (ty == 0) {
        float M = sm[0][tx], Sv = ss[0][tx];
        #pragma unroll
        for (int i = 1; i < 8; ++i) {
            float mi = sm[i][tx];
            float Mn = fmaxf(M, mi);
            Sv = Sv * __expf(M - Mn) + ss[i][tx] * __expf(mi - Mn);
            M = Mn;
        }
        sm[0][tx] = M;
        ss[0][tx] = 1.0f / Sv;
    }
    __syncthreads();

    const float M = sm[0][tx];
    const float invS = ss[0][tx];
    for (int p = ty; p < HW; p += 8) {
        size_t idx = (size_t)p * HW;
        col[idx] = __expf(col[idx] - M) * invS;
    }
}

// -------------------------------------------------------------------------
// Kernel 3: p_val[c][q] = sum_p V[c][p] * A[p][q]
// V layout: [nt][c][p] (p contiguous). A: [nt][p][q]. Out: [nt][c][q].
// -------------------------------------------------------------------------
__global__ __launch_bounds__(256) void pval_kernel(
    const float* __restrict__ V, const float* __restrict__ A,
    float* __restrict__ O)
{
    const int nt    = blockIdx.z;
    const int cBase = blockIdx.y * BM;
    const int qBase = blockIdx.x * BN;

    const float* Vb = V + (size_t)nt * C2 * HW;
    const float* Ab = A + (size_t)nt * HW * HW;
    float*       Ob = O + (size_t)nt * C2 * HW;

    __shared__ float As[BM][BK];   // [c][p]  (natural layout; broadcast reads)
    __shared__ float Bs[BK][BN];   // [p][q]

    const int tx = threadIdx.x;   // 0..15 (q)
    const int ty = threadIdx.y;   // 0..15 (c)
    const int tid = ty * 16 + tx;

    float acc[4][4];
    #pragma unroll
    for (int i = 0; i < 4; ++i)
        #pragma unroll
        for (int j = 0; j < 4; ++j) acc[i][j] = 0.f;

    const int arow = tid / 4;         // c 0..63
    const int ac4  = (tid % 4) * 4;   // p 0..12
    const int brow = tid / 16;        // p 0..15
    const int bc4  = (tid % 16) * 4;  // q

    for (int k0 = 0; k0 < HW; k0 += BK) {
        float4 a = *reinterpret_cast<const float4*>(&Vb[(size_t)(cBase + arow) * HW + k0 + ac4]);
        *reinterpret_cast<float4*>(&As[arow][ac4]) = a;
        float4 b = *reinterpret_cast<const float4*>(&Ab[(size_t)(k0 + brow) * HW + qBase + bc4]);
        *reinterpret_cast<float4*>(&Bs[brow][bc4]) = b;
        __syncthreads();

        #pragma unroll
        for (int kk = 0; kk < BK; ++kk) {
            float bv[4];
            *reinterpret_cast<float4*>(bv) = *reinterpret_cast<const float4*>(&Bs[kk][tx * 4]);
            #pragma unroll
            for (int i = 0; i < 4; ++i) {
                float av = As[ty * 4 + i][kk];
                #pragma unroll
                for (int j = 0; j < 4; ++j)
                    acc[i][j] = fmaf(av, bv[j], acc[i][j]);
            }
        }
        __syncthreads();
    }

    #pragma unroll
    for (int i = 0; i < 4; ++i) {
        const int c = cBase + ty * 4 + i;
        float4 v;
        v.x = acc[i][0];
        v.y = acc[i][1];
        v.z = acc[i][2];
        v.w = acc[i][3];
        *reinterpret_cast<float4*>(&Ob[(size_t)c * HW + qBase + tx * 4]) = v;
    }
}

// -------------------------------------------------------------------------
extern "C" void kernel_launch(void* const* d_in, const int* in_sizes, int n_in,
                              void* d_out, int out_size)
{
    const float* K = (const float*)d_in[0];   // key
    const float* Q = (const float*)d_in[1];   // query
    const float* V = (const float*)d_in[2];   // value

    float* out   = (float*)d_out;
    float* pval  = out;                 // [nt][c2][q]
    float* attn  = out + PVAL_ELEMS;    // [nt][p][q] — scores written here, softmaxed in place

    // 1) scores -> attn region
    {
        dim3 grid(HW / BN, HW / BM, NT);
        dim3 block(16, 16);
        scores_kernel<<<grid, block>>>(K, Q, attn);
    }
    // 2) softmax over p, in place
    {
        dim3 grid(HW / 32, NT);
        dim3 block(32, 8);
        softmax_p_kernel<<<grid, block>>>(attn);
    }
    // 3) p_val = V @ attn
    {
        dim3 grid(HW / BN, C2 / BM, NT);
        dim3 block(16, 16);
        pval_kernel<<<grid, block>>>(V, attn, pval);
    }
}

// round 2
// speedup vs baseline: 1.2829x; 1.2829x over previous
#include <cuda_runtime.h>
#include <cuda_bf16.h>
#include <math_constants.h>
#include <cstdint>

// Shapes (fixed by the problem)
#define NB 4
#define TB 8
#define NT (NB*TB)        // 32 batches
#define CC 256            // channels (reduction dim for scores)
#define C2 256            // value channels
#define HW 1024           // p == q == H*W
#define PVAL_ELEMS ((size_t)NT * C2 * HW)         // 8,388,608
#define ATTN_ELEMS ((size_t)NT * HW * HW)         // 33,554,432

#define KQV_ELEMS (NT * CC * HW)                  // 8,388,608 (int ok)

// ---- scratch: bf16 hi/lo splits (static __device__; no allocation) ----
__device__ __nv_bfloat16 g_khi[KQV_ELEMS];
__device__ __nv_bfloat16 g_klo[KQV_ELEMS];
__device__ __nv_bfloat16 g_qhi[KQV_ELEMS];
__device__ __nv_bfloat16 g_qlo[KQV_ELEMS];
__device__ __nv_bfloat16 g_vhi[KQV_ELEMS];
__device__ __nv_bfloat16 g_vlo[KQV_ELEMS];
__device__ __nv_bfloat16 g_ahi[NT * HW * HW];
__device__ __nv_bfloat16 g_alo[NT * HW * HW];

// ---------------------------------------------------------------------
// helpers
// ---------------------------------------------------------------------
__device__ __forceinline__ unsigned smaddr(const void* p) {
    return (unsigned)__cvta_generic_to_shared(p);
}

__device__ __forceinline__ void ldsm4(uint32_t* d, unsigned a) {
    asm volatile("ldmatrix.sync.aligned.m8n8.x4.shared.b16 {%0,%1,%2,%3}, [%4];"
                 : "=r"(d[0]), "=r"(d[1]), "=r"(d[2]), "=r"(d[3]) : "r"(a));
}
__device__ __forceinline__ void ldsm4t(uint32_t* d, unsigned a) {
    asm volatile("ldmatrix.sync.aligned.m8n8.x4.trans.shared.b16 {%0,%1,%2,%3}, [%4];"
                 : "=r"(d[0]), "=r"(d[1]), "=r"(d[2]), "=r"(d[3]) : "r"(a));
}
__device__ __forceinline__ void mma16816(float* d, const uint32_t* a, const uint32_t* b) {
    asm volatile("mma.sync.aligned.m16n8k16.row.col.f32.bf16.bf16.f32 "
                 "{%0,%1,%2,%3}, {%4,%5,%6,%7}, {%8,%9}, {%0,%1,%2,%3};"
                 : "+f"(d[0]), "+f"(d[1]), "+f"(d[2]), "+f"(d[3])
                 : "r"(a[0]), "r"(a[1]), "r"(a[2]), "r"(a[3]), "r"(b[0]), "r"(b[1]));
}

// ---------------------------------------------------------------------
// Kernel 0: split fp32 -> (bf16 hi, bf16 lo). which: 0=K 1=Q 2=V
// ---------------------------------------------------------------------
__global__ __launch_bounds__(256) void split_kernel(const float* __restrict__ src, int which)
{
    __nv_bfloat16 *hi, *lo;
    if (which == 0)      { hi = g_khi; lo = g_klo; }
    else if (which == 1) { hi = g_qhi; lo = g_qlo; }
    else                 { hi = g_vhi; lo = g_vlo; }

    int i = blockIdx.x * blockDim.x + threadIdx.x;
    int stride = gridDim.x * blockDim.x;
    for (; i < KQV_ELEMS / 4; i += stride) {
        float4 x = reinterpret_cast<const float4*>(src)[i];
        __nv_bfloat16 h0 = __float2bfloat16(x.x);
        __nv_bfloat16 h1 = __float2bfloat16(x.y);
        __nv_bfloat16 h2 = __float2bfloat16(x.z);
        __nv_bfloat16 h3 = __float2bfloat16(x.w);
        __nv_bfloat162 hh0 = {h0, h1}, hh1 = {h2, h3};
        __nv_bfloat162 ll0 = {__float2bfloat16(x.x - __bfloat162float(h0)),
                              __float2bfloat16(x.y - __bfloat162float(h1))};
        __nv_bfloat162 ll1 = {__float2bfloat16(x.z - __bfloat162float(h2)),
                              __float2bfloat16(x.w - __bfloat162float(h3))};
        reinterpret_cast<__nv_bfloat162*>(hi)[i * 2 + 0] = hh0;
        reinterpret_cast<__nv_bfloat162*>(hi)[i * 2 + 1] = hh1;
        reinterpret_cast<__nv_bfloat162*>(lo)[i * 2 + 0] = ll0;
        reinterpret_cast<__nv_bfloat162*>(lo)[i * 2 + 1] = ll1;
    }
}

// ---------------------------------------------------------------------
// Kernel 1: scores[p][q] = (1/16) * sum_c K[c][p]*Q[c][q]   (tensor cores)
// A = K^T (via trans ldmatrix of [c][p] tiles), B = Q (trans ldmatrix of [c][q]).
// Split-bf16: S = Ah*Bh + Ah*Bl + Al*Bh. Block 128x128, 8 warps (2m x 4n).
// ---------------------------------------------------------------------
__global__ __launch_bounds__(256) void scores_tc_kernel(float* __restrict__ S)
{
    const int nt    = blockIdx.z;
    const int pBase = blockIdx.y * 128;
    const int qBase = blockIdx.x * 128;

    __shared__ __nv_bfloat16 Ah[16][136], Al[16][136], Bh[16][136], Bl[16][136];

    const int tid  = threadIdx.x;
    const int lane = tid & 31;
    const int warp = tid >> 5;
    const int wm   = (warp & 1) * 64;
    const int wn   = (warp >> 1) * 32;

    float acc[4][4][4];
    #pragma unroll
    for (int i = 0; i < 4; ++i)
        #pragma unroll
        for (int j = 0; j < 4; ++j)
            #pragma unroll
            for (int k = 0; k < 4; ++k) acc[i][j][k] = 0.f;

    const int lrow = tid >> 4;          // 0..15 (c within chunk)
    const int lcol = (tid & 15) * 8;    // 0..120
    const size_t base = (size_t)nt * CC * HW;

    // ldmatrix lane-group geometry
    const int g = lane >> 3, r = lane & 7;
    const int arow  = r + ((g & 2) ? 8 : 0);   // A-trans: k row
    const int acolo = (g & 1) ? 8 : 0;         // A-trans: m col offset
    const int brow  = r + ((g & 1) ? 8 : 0);   // B-trans: k row
    const int bcolo = (g & 2) ? 8 : 0;         // B-trans: n col offset

    for (int k0 = 0; k0 < CC; k0 += 16) {
        const size_t rowoff = base + (size_t)(k0 + lrow) * HW;
        *(uint4*)&Ah[lrow][lcol] = *(const uint4*)&g_khi[rowoff + pBase + lcol];
        *(uint4*)&Al[lrow][lcol] = *(const uint4*)&g_klo[rowoff + pBase + lcol];
        *(uint4*)&Bh[lrow][lcol] = *(const uint4*)&g_qhi[rowoff + qBase + lcol];
        *(uint4*)&Bl[lrow][lcol] = *(const uint4*)&g_qlo[rowoff + qBase + lcol];
        __syncthreads();

        uint32_t af[4][4], bfh[4][2], bfl[4][2];

        #pragma unroll
        for (int mt = 0; mt < 4; ++mt)
            ldsm4t(af[mt], smaddr(&Ah[arow][wm + mt * 16 + acolo]));
        #pragma unroll
        for (int np = 0; np < 2; ++np) {
            uint32_t t[4];
            ldsm4t(t, smaddr(&Bh[brow][wn + np * 16 + bcolo]));
            bfh[np*2][0] = t[0]; bfh[np*2][1] = t[1];
            bfh[np*2+1][0] = t[2]; bfh[np*2+1][1] = t[3];
        }
        #pragma unroll
        for (int mt = 0; mt < 4; ++mt)
            #pragma unroll
            for (int ntile = 0; ntile < 4; ++ntile)
                mma16816(acc[mt][ntile], af[mt], bfh[ntile]);

        #pragma unroll
        for (int np = 0; np < 2; ++np) {
            uint32_t t[4];
            ldsm4t(t, smaddr(&Bl[brow][wn + np * 16 + bcolo]));
            bfl[np*2][0] = t[0]; bfl[np*2][1] = t[1];
            bfl[np*2+1][0] = t[2]; bfl[np*2+1][1] = t[3];
        }
        #pragma unroll
        for (int mt = 0; mt < 4; ++mt)
            #pragma unroll
            for (int ntile = 0; ntile < 4; ++ntile)
                mma16816(acc[mt][ntile], af[mt], bfl[ntile]);

        #pragma unroll
        for (int mt = 0; mt < 4; ++mt)
            ldsm4t(af[mt], smaddr(&Al[arow][wm + mt * 16 + acolo]));
        #pragma unroll
        for (int mt = 0; mt < 4; ++mt)
            #pragma unroll
            for (int ntile = 0; ntile < 4; ++ntile)
                mma16816(acc[mt][ntile], af[mt], bfh[ntile]);

        __syncthreads();
    }

    // epilogue: scale 1/16, store fp32
    float* Sb = S + (size_t)nt * HW * HW;
    const float sc = 1.0f / 16.0f;
    const int tr = lane >> 2;
    const int tc = (lane & 3) * 2;
    #pragma unroll
    for (int mt = 0; mt < 4; ++mt) {
        #pragma unroll
        for (int ntile = 0; ntile < 4; ++ntile) {
            const int m = pBase + wm + mt * 16 + tr;
            const int n = qBase + wn + ntile * 8 + tc;
            float2 v0 = {acc[mt][ntile][0] * sc, acc[mt][ntile][1] * sc};
            float2 v1 = {acc[mt][ntile][2] * sc, acc[mt][ntile][3] * sc};
            *(float2*)&Sb[(size_t)m * HW + n]       = v0;
            *(float2*)&Sb[(size_t)(m + 8) * HW + n] = v1;
        }
    }
}

// ---------------------------------------------------------------------
// Kernel 2: in-place softmax over p of S[nt][p][q]; also emit bf16 hi/lo
// of the normalized attention for the second GEMM.
// ---------------------------------------------------------------------
__global__ __launch_bounds__(256) void softmax_p_kernel(float* __restrict__ S)
{
    const int nt = blockIdx.y;
    const int tx = threadIdx.x;              // 0..31  -> q within tile
    const int ty = threadIdx.y;              // 0..7   -> p stripe
    const int q  = blockIdx.x * 32 + tx;

    const size_t colbase = (size_t)nt * HW * HW + q;
    float* col = S + colbase;

    float m = -CUDART_INF_F;
    float s = 0.f;
    for (int p = ty; p < HW; p += 8) {
        float x = col[(size_t)p * HW];
        float mn = fmaxf(m, x);
        s = s * __expf(m - mn) + __expf(x - mn);
        m = mn;
    }

    __shared__ float sm[8][32];
    __shared__ float ss[8][32];
    sm[ty][tx] = m;
    ss[ty][tx] = s;
    __syncthreads();

    if (ty == 0) {
        float M = sm[0][tx], Sv = ss[0][tx];
        #pragma unroll
        for (int i = 1; i < 8; ++i) {
            float mi = sm[i][tx];
            float Mn = fmaxf(M, mi);
            Sv = Sv * __expf(M - Mn) + ss[i][tx] * __expf(mi - Mn);
            M = Mn;
        }
        sm[0][tx] = M;
        ss[0][tx] = 1.0f / Sv;
    }
    __syncthreads();

    const float M = sm[0][tx];
    const float invS = ss[0][tx];
    for (int p = ty; p < HW; p += 8) {
        size_t idx = (size_t)p * HW;
        float a = __expf(col[idx] - M) * invS;
        col[idx] = a;
        __nv_bfloat16 h = __float2bfloat16(a);
        g_ahi[colbase + idx] = h;
        g_alo[colbase + idx] = __float2bfloat16(a - __bfloat162float(h));
    }
}

// ---------------------------------------------------------------------
// Kernel 3: p_val[c][q] = sum_p V[c][p] * A[p][q]  (tensor cores)
// A = V [c][p] row-major (non-trans ldmatrix), B = attn [p][q] (trans).
// Split-bf16 3-product. Block 128x128, 8 warps (2m x 4n).
// ---------------------------------------------------------------------
__global__ __launch_bounds__(256) void pval_tc_kernel(float* __restrict__ O)
{
    const int nt    = blockIdx.z;
    const int cBase = blockIdx.y * 128;
    const int qBase = blockIdx.x * 128;

    __shared__ __nv_bfloat16 Vh[128][24], Vl[128][24], Th[16][136], Tl[16][136];

    const int tid  = threadIdx.x;
    const int lane = tid & 31;
    const int warp = tid >> 5;
    const int wm   = (warp & 1) * 64;
    const int wn   = (warp >> 1) * 32;

    float acc[4][4][4];
    #pragma unroll
    for (int i = 0; i < 4; ++i)
        #pragma unroll
        for (int j = 0; j < 4; ++j)
            #pragma unroll
            for (int k = 0; k < 4; ++k) acc[i][j][k] = 0.f;

    // V tile loads: 128 rows x 16 cols; one uint4 (8 bf16) per half-row
    const int vrow = tid >> 1;
    const int vcol = (tid & 1) * 8;
    // attn tile loads: 16 rows x 128 cols
    const int trow = tid >> 4;
    const int tcol = (tid & 15) * 8;

    const size_t vbase = (size_t)nt * C2 * HW;
    const size_t abase = (size_t)nt * HW * HW;

    const int g = lane >> 3, r = lane & 7;
    // A non-trans: row = m + r (+8 for g1/g3), col = 0 or 8
    const int amro  = r + ((g & 1) ? 8 : 0);
    const int acolo = (g & 2) ? 8 : 0;
    // B-trans
    const int brow  = r + ((g & 1) ? 8 : 0);
    const int bcolo = (g & 2) ? 8 : 0;

    for (int k0 = 0; k0 < HW; k0 += 16) {
        const size_t vrowoff = vbase + (size_t)(cBase + vrow) * HW + k0 + vcol;
        *(uint4*)&Vh[vrow][vcol] = *(const uint4*)&g_vhi[vrowoff];
        *(uint4*)&Vl[vrow][vcol] = *(const uint4*)&g_vlo[vrowoff];
        const size_t arowoff = abase + (size_t)(k0 + trow) * HW + qBase + tcol;
        *(uint4*)&Th[trow][tcol] = *(const uint4*)&g_ahi[arowoff];
        *(uint4*)&Tl[trow][tcol] = *(const uint4*)&g_alo[arowoff];
        __syncthreads();

        uint32_t af[4][4], bfh[4][2], bfl[4][2];

        #pragma unroll
        for (int mt = 0; mt < 4; ++mt)
            ldsm4(af[mt], smaddr(&Vh[wm + mt * 16 + amro][acolo]));
        #pragma unroll
        for (int np = 0; np < 2; ++np) {
            uint32_t t[4];
            ldsm4t(t, smaddr(&Th[brow][wn + np * 16 + bcolo]));
            bfh[np*2][0] = t[0]; bfh[np*2][1] = t[1];
            bfh[np*2+1][0] = t[2]; bfh[np*2+1][1] = t[3];
        }
        #pragma unroll
        for (int mt = 0; mt < 4; ++mt)
            #pragma unroll
            for (int ntile = 0; ntile < 4; ++ntile)
                mma16816(acc[mt][ntile], af[mt], bfh[ntile]);

        #pragma unroll
        for (int np = 0; np < 2; ++np) {
            uint32_t t[4];
            ldsm4t(t, smaddr(&Tl[brow][wn + np * 16 + bcolo]));
            bfl[np*2][0] = t[0]; bfl[np*2][1] = t[1];
            bfl[np*2+1][0] = t[2]; bfl[np*2+1][1] = t[3];
        }
        #pragma unroll
        for (int mt = 0; mt < 4; ++mt)
            #pragma unroll
            for (int ntile = 0; ntile < 4; ++ntile)
                mma16816(acc[mt][ntile], af[mt], bfl[ntile]);

        #pragma unroll
        for (int mt = 0; mt < 4; ++mt)
            ldsm4(af[mt], smaddr(&Vl[wm + mt * 16 + amro][acolo]));
        #pragma unroll
        for (int mt = 0; mt < 4; ++mt)
            #pragma unroll
            for (int ntile = 0; ntile < 4; ++ntile)
                mma16816(acc[mt][ntile], af[mt], bfh[ntile]);

        __syncthreads();
    }

    float* Ob = O + (size_t)nt * C2 * HW;
    const int tr = lane >> 2;
    const int tc = (lane & 3) * 2;
    #pragma unroll
    for (int mt = 0; mt < 4; ++mt) {
        #pragma unroll
        for (int ntile = 0; ntile < 4; ++ntile) {
            const int m = cBase + wm + mt * 16 + tr;
            const int n = qBase + wn + ntile * 8 + tc;
            float2 v0 = {acc[mt][ntile][0], acc[mt][ntile][1]};
            float2 v1 = {acc[mt][ntile][2], acc[mt][ntile][3]};
            *(float2*)&Ob[(size_t)m * HW + n]       = v0;
            *(float2*)&Ob[(size_t)(m + 8) * HW + n] = v1;
        }
    }
}

// ---------------------------------------------------------------------
extern "C" void kernel_launch(void* const* d_in, const int* in_sizes, int n_in,
                              void* d_out, int out_size)
{
    const float* K = (const float*)d_in[0];   // key
    const float* Q = (const float*)d_in[1];   // query
    const float* V = (const float*)d_in[2];   // value

    float* out  = (float*)d_out;
    float* pval = out;                 // [nt][c2][q]
    float* attn = out + PVAL_ELEMS;    // [nt][p][q]

    // 0) fp32 -> bf16 hi/lo splits
    split_kernel<<<1024, 256>>>(K, 0);
    split_kernel<<<1024, 256>>>(Q, 1);
    split_kernel<<<1024, 256>>>(V, 2);

    // 1) scores -> attn region (tensor cores, split-bf16)
    {
        dim3 grid(HW / 128, HW / 128, NT);
        scores_tc_kernel<<<grid, 256>>>(attn);
    }
    // 2) softmax over p, in place; emit bf16 hi/lo attn
    {
        dim3 grid(HW / 32, NT);
        dim3 block(32, 8);
        softmax_p_kernel<<<grid, block>>>(attn);
    }
    // 3) p_val = V @ attn (tensor cores, split-bf16)
    {
        dim3 grid(HW / 128, C2 / 128, NT);
        pval_tc_kernel<<<grid, 256>>>(pval);
    }
}

// round 3
// speedup vs baseline: 1.9872x; 1.5490x over previous
#include <cuda_runtime.h>
#include <cuda_bf16.h>
#include <math_constants.h>
#include <cstdint>

// Shapes (fixed by the problem)
#define NB 4
#define TB 8
#define NT (NB*TB)        // 32 batches
#define CC 256            // channels (reduction dim for scores)
#define C2 256            // value channels
#define HW 1024           // p == q == H*W
#define PVAL_ELEMS ((size_t)NT * C2 * HW)         // 8,388,608
#define KQV_ELEMS (NT * CC * HW)                  // 8,388,608

// ---- scratch: bf16 hi/lo splits (static __device__; no allocation) ----
__device__ __nv_bfloat16 g_khi[KQV_ELEMS];
__device__ __nv_bfloat16 g_klo[KQV_ELEMS];
__device__ __nv_bfloat16 g_qhi[KQV_ELEMS];
__device__ __nv_bfloat16 g_qlo[KQV_ELEMS];
__device__ __nv_bfloat16 g_vhi[KQV_ELEMS];
__device__ __nv_bfloat16 g_vlo[KQV_ELEMS];
__device__ __nv_bfloat16 g_ahi[NT * HW * HW];
__device__ __nv_bfloat16 g_alo[NT * HW * HW];

// ---------------------------------------------------------------------
// helpers
// ---------------------------------------------------------------------
__device__ __forceinline__ unsigned smaddr(const void* p) {
    return (unsigned)__cvta_generic_to_shared(p);
}
__device__ __forceinline__ void ldsm4(uint32_t* d, unsigned a) {
    asm volatile("ldmatrix.sync.aligned.m8n8.x4.shared.b16 {%0,%1,%2,%3}, [%4];"
                 : "=r"(d[0]), "=r"(d[1]), "=r"(d[2]), "=r"(d[3]) : "r"(a));
}
__device__ __forceinline__ void ldsm4t(uint32_t* d, unsigned a) {
    asm volatile("ldmatrix.sync.aligned.m8n8.x4.trans.shared.b16 {%0,%1,%2,%3}, [%4];"
                 : "=r"(d[0]), "=r"(d[1]), "=r"(d[2]), "=r"(d[3]) : "r"(a));
}
__device__ __forceinline__ void mma16816(float* d, const uint32_t* a, const uint32_t* b) {
    asm volatile("mma.sync.aligned.m16n8k16.row.col.f32.bf16.bf16.f32 "
                 "{%0,%1,%2,%3}, {%4,%5,%6,%7}, {%8,%9}, {%0,%1,%2,%3};"
                 : "+f"(d[0]), "+f"(d[1]), "+f"(d[2]), "+f"(d[3])
                 : "r"(a[0]), "r"(a[1]), "r"(a[2]), "r"(a[3]), "r"(b[0]), "r"(b[1]));
}
__device__ __forceinline__ void cpasync16(void* dst, const void* src) {
    unsigned d = smaddr(dst);
    asm volatile("cp.async.cg.shared.global [%0], [%1], 16;" :: "r"(d), "l"(src));
}
__device__ __forceinline__ void cp_commit() {
    asm volatile("cp.async.commit_group;");
}
template <int N>
__device__ __forceinline__ void cp_wait() {
    asm volatile("cp.async.wait_group %0;" :: "n"(N));
}

// ---------------------------------------------------------------------
// Kernel 0: split fp32 -> (bf16 hi, bf16 lo) for K, Q, V in one launch.
// blockIdx.y selects the tensor.
// ---------------------------------------------------------------------
__global__ __launch_bounds__(256) void split_kernel(
    const float* __restrict__ K, const float* __restrict__ Q, const float* __restrict__ V)
{
    const float* src;
    __nv_bfloat16 *hi, *lo;
    if (blockIdx.y == 0)      { src = K; hi = g_khi; lo = g_klo; }
    else if (blockIdx.y == 1) { src = Q; hi = g_qhi; lo = g_qlo; }
    else                      { src = V; hi = g_vhi; lo = g_vlo; }

    int i = blockIdx.x * blockDim.x + threadIdx.x;
    int stride = gridDim.x * blockDim.x;
    for (; i < KQV_ELEMS / 4; i += stride) {
        float4 x = reinterpret_cast<const float4*>(src)[i];
        __nv_bfloat16 h0 = __float2bfloat16(x.x);
        __nv_bfloat16 h1 = __float2bfloat16(x.y);
        __nv_bfloat16 h2 = __float2bfloat16(x.z);
        __nv_bfloat16 h3 = __float2bfloat16(x.w);
        __nv_bfloat162 hh0 = {h0, h1}, hh1 = {h2, h3};
        __nv_bfloat162 ll0 = {__float2bfloat16(x.x - __bfloat162float(h0)),
                              __float2bfloat16(x.y - __bfloat162float(h1))};
        __nv_bfloat162 ll1 = {__float2bfloat16(x.z - __bfloat162float(h2)),
                              __float2bfloat16(x.w - __bfloat162float(h3))};
        reinterpret_cast<__nv_bfloat162*>(hi)[i * 2 + 0] = hh0;
        reinterpret_cast<__nv_bfloat162*>(hi)[i * 2 + 1] = hh1;
        reinterpret_cast<__nv_bfloat162*>(lo)[i * 2 + 0] = ll0;
        reinterpret_cast<__nv_bfloat162*>(lo)[i * 2 + 1] = ll1;
    }
}

// ---------------------------------------------------------------------
// Kernel 1: scores[p][q] = (1/16) * sum_c K[c][p]*Q[c][q]
// Tensor cores + split-bf16 (Ah*Bh + Ah*Bl + Al*Bh).
// cp.async double-buffered pipeline, BK=16, block 128x128, 8 warps.
// ---------------------------------------------------------------------
__global__ __launch_bounds__(256) void scores_tc_kernel(float* __restrict__ S)
{
    const int nt    = blockIdx.z;
    const int pBase = blockIdx.y * 128;
    const int qBase = blockIdx.x * 128;

    __shared__ __nv_bfloat16 Ah[2][16][136], Al[2][16][136];
    __shared__ __nv_bfloat16 Bh[2][16][136], Bl[2][16][136];

    const int tid  = threadIdx.x;
    const int lane = tid & 31;
    const int warp = tid >> 5;
    const int wm   = (warp & 1) * 64;
    const int wn   = (warp >> 1) * 32;

    float acc[4][4][4];
    #pragma unroll
    for (int i = 0; i < 4; ++i)
        #pragma unroll
        for (int j = 0; j < 4; ++j)
            #pragma unroll
            for (int k = 0; k < 4; ++k) acc[i][j][k] = 0.f;

    const int lrow = tid >> 4;          // 0..15 (c within chunk)
    const int lcol = (tid & 15) * 8;    // 0..120
    const size_t base = (size_t)nt * CC * HW;

    // ldmatrix lane-group geometry
    const int g = lane >> 3, r = lane & 7;
    const int arow  = r + ((g & 2) ? 8 : 0);   // A-trans: k row
    const int acolo = (g & 1) ? 8 : 0;         // A-trans: m col offset
    const int brow  = r + ((g & 1) ? 8 : 0);   // B-trans: k row
    const int bcolo = (g & 2) ? 8 : 0;         // B-trans: n col offset

    // prefetch chunk 0
    {
        const size_t rowoff = base + (size_t)lrow * HW;
        cpasync16(&Ah[0][lrow][lcol], &g_khi[rowoff + pBase + lcol]);
        cpasync16(&Al[0][lrow][lcol], &g_klo[rowoff + pBase + lcol]);
        cpasync16(&Bh[0][lrow][lcol], &g_qhi[rowoff + qBase + lcol]);
        cpasync16(&Bl[0][lrow][lcol], &g_qlo[rowoff + qBase + lcol]);
        cp_commit();
    }

    #pragma unroll 1
    for (int it = 0; it < CC / 16; ++it) {
        if (it < CC / 16 - 1) {
            const int s1 = (it + 1) & 1;
            const size_t rowoff = base + (size_t)((it + 1) * 16 + lrow) * HW;
            cpasync16(&Ah[s1][lrow][lcol], &g_khi[rowoff + pBase + lcol]);
            cpasync16(&Al[s1][lrow][lcol], &g_klo[rowoff + pBase + lcol]);
            cpasync16(&Bh[s1][lrow][lcol], &g_qhi[rowoff + qBase + lcol]);
            cpasync16(&Bl[s1][lrow][lcol], &g_qlo[rowoff + qBase + lcol]);
            cp_commit();
            cp_wait<1>();
        } else {
            cp_wait<0>();
        }
        __syncthreads();

        const int s = it & 1;
        uint32_t af[4][4], bfh[4][2], bfl[4][2];

        #pragma unroll
        for (int mt = 0; mt < 4; ++mt)
            ldsm4t(af[mt], smaddr(&Ah[s][arow][wm + mt * 16 + acolo]));
        #pragma unroll
        for (int np = 0; np < 2; ++np) {
            uint32_t t[4];
            ldsm4t(t, smaddr(&Bh[s][brow][wn + np * 16 + bcolo]));
            bfh[np*2][0] = t[0]; bfh[np*2][1] = t[1];
            bfh[np*2+1][0] = t[2]; bfh[np*2+1][1] = t[3];
        }
        #pragma unroll
        for (int mt = 0; mt < 4; ++mt)
            #pragma unroll
            for (int nn = 0; nn < 4; ++nn)
                mma16816(acc[mt][nn], af[mt], bfh[nn]);

        #pragma unroll
        for (int np = 0; np < 2; ++np) {
            uint32_t t[4];
            ldsm4t(t, smaddr(&Bl[s][brow][wn + np * 16 + bcolo]));
            bfl[np*2][0] = t[0]; bfl[np*2][1] = t[1];
            bfl[np*2+1][0] = t[2]; bfl[np*2+1][1] = t[3];
        }
        #pragma unroll
        for (int mt = 0; mt < 4; ++mt)
            #pragma unroll
            for (int nn = 0; nn < 4; ++nn)
                mma16816(acc[mt][nn], af[mt], bfl[nn]);

        #pragma unroll
        for (int mt = 0; mt < 4; ++mt)
            ldsm4t(af[mt], smaddr(&Al[s][arow][wm + mt * 16 + acolo]));
        #pragma unroll
        for (int mt = 0; mt < 4; ++mt)
            #pragma unroll
            for (int nn = 0; nn < 4; ++nn)
                mma16816(acc[mt][nn], af[mt], bfh[nn]);

        __syncthreads();
    }

    // epilogue: scale 1/16, store fp32
    float* Sb = S + (size_t)nt * HW * HW;
    const float sc = 1.0f / 16.0f;
    const int tr = lane >> 2;
    const int tc = (lane & 3) * 2;
    #pragma unroll
    for (int mt = 0; mt < 4; ++mt) {
        #pragma unroll
        for (int nn = 0; nn < 4; ++nn) {
            const int m = pBase + wm + mt * 16 + tr;
            const int n = qBase + wn + nn * 8 + tc;
            float2 v0 = {acc[mt][nn][0] * sc, acc[mt][nn][1] * sc};
            float2 v1 = {acc[mt][nn][2] * sc, acc[mt][nn][3] * sc};
            *(float2*)&Sb[(size_t)m * HW + n]       = v0;
            *(float2*)&Sb[(size_t)(m + 8) * HW + n] = v1;
        }
    }
}

// ---------------------------------------------------------------------
// Kernel 2: in-place softmax over p of S[nt][p][q]; also emit bf16 hi/lo
// of the normalized attention for the second GEMM.
// ---------------------------------------------------------------------
__global__ __launch_bounds__(256) void softmax_p_kernel(float* __restrict__ S)
{
    const int nt = blockIdx.y;
    const int tx = threadIdx.x;              // 0..31  -> q within tile
    const int ty = threadIdx.y;              // 0..7   -> p stripe
    const int q  = blockIdx.x * 32 + tx;

    const size_t colbase = (size_t)nt * HW * HW + q;
    float* col = S + colbase;

    float m = -CUDART_INF_F;
    float s = 0.f;
    for (int p = ty; p < HW; p += 8) {
        float x = col[(size_t)p * HW];
        float mn = fmaxf(m, x);
        s = s * __expf(m - mn) + __expf(x - mn);
        m = mn;
    }

    __shared__ float sm[8][32];
    __shared__ float ss[8][32];
    sm[ty][tx] = m;
    ss[ty][tx] = s;
    __syncthreads();

    if (ty == 0) {
        float M = sm[0][tx], Sv = ss[0][tx];
        #pragma unroll
        for (int i = 1; i < 8; ++i) {
            float mi = sm[i][tx];
            float Mn = fmaxf(M, mi);
            Sv = Sv * __expf(M - Mn) + ss[i][tx] * __expf(mi - Mn);
            M = Mn;
        }
        sm[0][tx] = M;
        ss[0][tx] = 1.0f / Sv;
    }
    __syncthreads();

    const float M = sm[0][tx];
    const float invS = ss[0][tx];
    for (int p = ty; p < HW; p += 8) {
        size_t idx = (size_t)p * HW;
        float a = __expf(col[idx] - M) * invS;
        col[idx] = a;
        __nv_bfloat16 h = __float2bfloat16(a);
        g_ahi[colbase + idx] = h;
        g_alo[colbase + idx] = __float2bfloat16(a - __bfloat162float(h));
    }
}

// ---------------------------------------------------------------------
// Kernel 3: p_val[c][q] = sum_p V[c][p] * A[p][q]
// Tensor cores + split-bf16; cp.async double-buffered, BK=16.
// ---------------------------------------------------------------------
__global__ __launch_bounds__(256) void pval_tc_kernel(float* __restrict__ O)
{
    const int nt    = blockIdx.z;
    const int cBase = blockIdx.y * 128;
    const int qBase = blockIdx.x * 128;

    __shared__ __nv_bfloat16 Vh[2][128][24], Vl[2][128][24];
    __shared__ __nv_bfloat16 Th[2][16][136], Tl[2][16][136];

    const int tid  = threadIdx.x;
    const int lane = tid & 31;
    const int warp = tid >> 5;
    const int wm   = (warp & 1) * 64;
    const int wn   = (warp >> 1) * 32;

    float acc[4][4][4];
    #pragma unroll
    for (int i = 0; i < 4; ++i)
        #pragma unroll
        for (int j = 0; j < 4; ++j)
            #pragma unroll
            for (int k = 0; k < 4; ++k) acc[i][j][k] = 0.f;

    const int vrow = tid >> 1;        // 0..127
    const int vcol = (tid & 1) * 8;   // 0 or 8
    const int trow = tid >> 4;        // 0..15
    const int tcol = (tid & 15) * 8;  // 0..120

    const size_t vbase = (size_t)nt * C2 * HW;
    const size_t abase = (size_t)nt * HW * HW;

    const int g = lane >> 3, r = lane & 7;
    const int amro  = r + ((g & 1) ? 8 : 0);   // A non-trans row offset
    const int acolo = (g & 2) ? 8 : 0;
    const int brow  = r + ((g & 1) ? 8 : 0);   // B-trans
    const int bcolo = (g & 2) ? 8 : 0;

    // prefetch chunk 0
    {
        const size_t vo = vbase + (size_t)(cBase + vrow) * HW + vcol;
        cpasync16(&Vh[0][vrow][vcol], &g_vhi[vo]);
        cpasync16(&Vl[0][vrow][vcol], &g_vlo[vo]);
        const size_t ao = abase + (size_t)trow * HW + qBase + tcol;
        cpasync16(&Th[0][trow][tcol], &g_ahi[ao]);
        cpasync16(&Tl[0][trow][tcol], &g_alo[ao]);
        cp_commit();
    }

    #pragma unroll 1
    for (int it = 0; it < HW / 16; ++it) {
        if (it < HW / 16 - 1) {
            const int s1 = (it + 1) & 1;
            const int k1 = (it + 1) * 16;
            const size_t vo = vbase + (size_t)(cBase + vrow) * HW + k1 + vcol;
            cpasync16(&Vh[s1][vrow][vcol], &g_vhi[vo]);
            cpasync16(&Vl[s1][vrow][vcol], &g_vlo[vo]);
            const size_t ao = abase + (size_t)(k1 + trow) * HW + qBase + tcol;
            cpasync16(&Th[s1][trow][tcol], &g_ahi[ao]);
            cpasync16(&Tl[s1][trow][tcol], &g_alo[ao]);
            cp_commit();
            cp_wait<1>();
        } else {
            cp_wait<0>();
        }
        __syncthreads();

        const int s = it & 1;
        uint32_t af[4][4], bfh[4][2], bfl[4][2];

        #pragma unroll
        for (int mt = 0; mt < 4; ++mt)
            ldsm4(af[mt], smaddr(&Vh[s][wm + mt * 16 + amro][acolo]));
        #pragma unroll
        for (int np = 0; np < 2; ++np) {
            uint32_t t[4];
            ldsm4t(t, smaddr(&Th[s][brow][wn + np * 16 + bcolo]));
            bfh[np*2][0] = t[0]; bfh[np*2][1] = t[1];
            bfh[np*2+1][0] = t[2]; bfh[np*2+1][1] = t[3];
        }
        #pragma unroll
        for (int mt = 0; mt < 4; ++mt)
            #pragma unroll
            for (int nn = 0; nn < 4; ++nn)
                mma16816(acc[mt][nn], af[mt], bfh[nn]);

        #pragma unroll
        for (int np = 0; np < 2; ++np) {
            uint32_t t[4];
            ldsm4t(t, smaddr(&Tl[s][brow][wn + np * 16 + bcolo]));
            bfl[np*2][0] = t[0]; bfl[np*2][1] = t[1];
            bfl[np*2+1][0] = t[2]; bfl[np*2+1][1] = t[3];
        }
        #pragma unroll
        for (int mt = 0; mt < 4; ++mt)
            #pragma unroll
            for (int nn = 0; nn < 4; ++nn)
                mma16816(acc[mt][nn], af[mt], bfl[nn]);

        #pragma unroll
        for (int mt = 0; mt < 4; ++mt)
            ldsm4(af[mt], smaddr(&Vl[s][wm + mt * 16 + amro][acolo]));
        #pragma unroll
        for (int mt = 0; mt < 4; ++mt)
            #pragma unroll
            for (int nn = 0; nn < 4; ++nn)
                mma16816(acc[mt][nn], af[mt], bfh[nn]);

        __syncthreads();
    }

    float* Ob = O + (size_t)nt * C2 * HW;
    const int tr = lane >> 2;
    const int tc = (lane & 3) * 2;
    #pragma unroll
    for (int mt = 0; mt < 4; ++mt) {
        #pragma unroll
        for (int nn = 0; nn < 4; ++nn) {
            const int m = cBase + wm + mt * 16 + tr;
            const int n = qBase + wn + nn * 8 + tc;
            float2 v0 = {acc[mt][nn][0], acc[mt][nn][1]};
            float2 v1 = {acc[mt][nn][2], acc[mt][nn][3]};
            *(float2*)&Ob[(size_t)m * HW + n]       = v0;
            *(float2*)&Ob[(size_t)(m + 8) * HW + n] = v1;
        }
    }
}

// ---------------------------------------------------------------------
extern "C" void kernel_launch(void* const* d_in, const int* in_sizes, int n_in,
                              void* d_out, int out_size)
{
    const float* K = (const float*)d_in[0];   // key
    const float* Q = (const float*)d_in[1];   // query
    const float* V = (const float*)d_in[2];   // value

    float* out  = (float*)d_out;
    float* pval = out;                 // [nt][c2][q]
    float* attn = out + PVAL_ELEMS;    // [nt][p][q]

    // 0) fp32 -> bf16 hi/lo splits (K, Q, V in one launch)
    {
        dim3 grid(512, 3);
        split_kernel<<<grid, 256>>>(K, Q, V);
    }
    // 1) scores -> attn region (tensor cores, split-bf16, pipelined)
    {
        dim3 grid(HW / 128, HW / 128, NT);
        scores_tc_kernel<<<grid, 256>>>(attn);
    }
    // 2) softmax over p, in place; emit bf16 hi/lo attn
    {
        dim3 grid(HW / 32, NT);
        dim3 block(32, 8);
        softmax_p_kernel<<<grid, block>>>(attn);
    }
    // 3) p_val = V @ attn (tensor cores, split-bf16, pipelined)
    {
        dim3 grid(HW / 128, C2 / 128, NT);
        pval_tc_kernel<<<grid, 256>>>(pval);
    }
}

// round 4
// speedup vs baseline: 2.2882x; 1.1515x over previous
#include <cuda_runtime.h>
#include <cuda_bf16.h>
#include <math_constants.h>
#include <cstdint>

// Shapes (fixed by the problem)
#define NB 4
#define TB 8
#define NT (NB*TB)        // 32 batches
#define CC 256            // channels (reduction dim for scores)
#define C2 256            // value channels
#define HW 1024           // p == q == H*W
#define PVAL_ELEMS ((size_t)NT * C2 * HW)         // 8,388,608
#define KQV_ELEMS (NT * CC * HW)                  // 8,388,608

// ---- scratch (static __device__; no allocation) ----
__device__ __nv_bfloat16 g_khi[KQV_ELEMS];
__device__ __nv_bfloat16 g_klo[KQV_ELEMS];
__device__ __nv_bfloat16 g_qhi[KQV_ELEMS];
__device__ __nv_bfloat16 g_qlo[KQV_ELEMS];
__device__ __nv_bfloat16 g_vhi[KQV_ELEMS];
__device__ __nv_bfloat16 g_vlo[KQV_ELEMS];
__device__ __nv_bfloat16 g_ehi[(size_t)NT * HW * HW];   // exp(scores) hi
__device__ __nv_bfloat16 g_elo[(size_t)NT * HW * HW];   // exp(scores) lo
__device__ float g_partial[(size_t)NT * 16 * HW];       // per (ptile,mhalf) column sums
__device__ float g_inv[NT * HW];                        // 1 / column sum

// ---------------------------------------------------------------------
// helpers
// ---------------------------------------------------------------------
__device__ __forceinline__ unsigned smaddr(const void* p) {
    return (unsigned)__cvta_generic_to_shared(p);
}
__device__ __forceinline__ void ldsm4(uint32_t* d, unsigned a) {
    asm volatile("ldmatrix.sync.aligned.m8n8.x4.shared.b16 {%0,%1,%2,%3}, [%4];"
                 : "=r"(d[0]), "=r"(d[1]), "=r"(d[2]), "=r"(d[3]) : "r"(a));
}
__device__ __forceinline__ void ldsm4t(uint32_t* d, unsigned a) {
    asm volatile("ldmatrix.sync.aligned.m8n8.x4.trans.shared.b16 {%0,%1,%2,%3}, [%4];"
                 : "=r"(d[0]), "=r"(d[1]), "=r"(d[2]), "=r"(d[3]) : "r"(a));
}
__device__ __forceinline__ void mma16816(float* d, const uint32_t* a, const uint32_t* b) {
    asm volatile("mma.sync.aligned.m16n8k16.row.col.f32.bf16.bf16.f32 "
                 "{%0,%1,%2,%3}, {%4,%5,%6,%7}, {%8,%9}, {%0,%1,%2,%3};"
                 : "+f"(d[0]), "+f"(d[1]), "+f"(d[2]), "+f"(d[3])
                 : "r"(a[0]), "r"(a[1]), "r"(a[2]), "r"(a[3]), "r"(b[0]), "r"(b[1]));
}
__device__ __forceinline__ void cpasync16(void* dst, const void* src) {
    unsigned d = smaddr(dst);
    asm volatile("cp.async.cg.shared.global [%0], [%1], 16;" :: "r"(d), "l"(src));
}
__device__ __forceinline__ void cp_commit() {
    asm volatile("cp.async.commit_group;");
}
template <int N>
__device__ __forceinline__ void cp_wait() {
    asm volatile("cp.async.wait_group %0;" :: "n"(N));
}

// ---------------------------------------------------------------------
// Kernel 0: split fp32 -> (bf16 hi, bf16 lo) for K, Q, V.
// ---------------------------------------------------------------------
__global__ __launch_bounds__(256) void split_kernel(
    const float* __restrict__ K, const float* __restrict__ Q, const float* __restrict__ V)
{
    const float* src;
    __nv_bfloat16 *hi, *lo;
    if (blockIdx.y == 0)      { src = K; hi = g_khi; lo = g_klo; }
    else if (blockIdx.y == 1) { src = Q; hi = g_qhi; lo = g_qlo; }
    else                      { src = V; hi = g_vhi; lo = g_vlo; }

    int i = blockIdx.x * blockDim.x + threadIdx.x;
    int stride = gridDim.x * blockDim.x;
    for (; i < KQV_ELEMS / 4; i += stride) {
        float4 x = reinterpret_cast<const float4*>(src)[i];
        __nv_bfloat16 h0 = __float2bfloat16(x.x);
        __nv_bfloat16 h1 = __float2bfloat16(x.y);
        __nv_bfloat16 h2 = __float2bfloat16(x.z);
        __nv_bfloat16 h3 = __float2bfloat16(x.w);
        __nv_bfloat162 hh0 = {h0, h1}, hh1 = {h2, h3};
        __nv_bfloat162 ll0 = {__float2bfloat16(x.x - __bfloat162float(h0)),
                              __float2bfloat16(x.y - __bfloat162float(h1))};
        __nv_bfloat162 ll1 = {__float2bfloat16(x.z - __bfloat162float(h2)),
                              __float2bfloat16(x.w - __bfloat162float(h3))};
        reinterpret_cast<__nv_bfloat162*>(hi)[i * 2 + 0] = hh0;
        reinterpret_cast<__nv_bfloat162*>(hi)[i * 2 + 1] = hh1;
        reinterpret_cast<__nv_bfloat162*>(lo)[i * 2 + 0] = ll0;
        reinterpret_cast<__nv_bfloat162*>(lo)[i * 2 + 1] = ll1;
    }
}

// ---------------------------------------------------------------------
// Kernel 1: e[p][q] = exp( (1/16) * sum_c K[c][p]*Q[c][q] )
// Emits bf16 hi/lo of e and deterministic per-(ptile,mhalf) column sums.
// Tensor cores + split-bf16; BK=32, 3-stage cp.async pipeline.
// ---------------------------------------------------------------------
struct ScoresStage {
    __nv_bfloat16 Ah[32][136], Al[32][136], Bh[32][136], Bl[32][136];
};

__global__ __launch_bounds__(256, 2) void scores_tc_kernel()
{
    extern __shared__ char dynsmem[];
    ScoresStage* stg = reinterpret_cast<ScoresStage*>(dynsmem);

    const int nt    = blockIdx.z;
    const int pBase = blockIdx.y * 128;
    const int qBase = blockIdx.x * 128;

    const int tid  = threadIdx.x;
    const int lane = tid & 31;
    const int warp = tid >> 5;
    const int wm   = (warp & 1) * 64;
    const int wn   = (warp >> 1) * 32;

    float acc[4][4][4];
    #pragma unroll
    for (int i = 0; i < 4; ++i)
        #pragma unroll
        for (int j = 0; j < 4; ++j)
            #pragma unroll
            for (int k = 0; k < 4; ++k) acc[i][j][k] = 0.f;

    const size_t base = (size_t)nt * CC * HW;

    // loader geometry: 512 vec8 per array per chunk; 2 per thread
    const int v0   = tid * 2;
    const int lr0  = v0 >> 4;
    const int lc0  = (v0 & 15) * 8;
    const int lr1  = (v0 + 1) >> 4;
    const int lc1  = ((v0 + 1) & 15) * 8;

    // ldmatrix lane-group geometry
    const int g = lane >> 3, r = lane & 7;
    const int arow  = r + ((g & 2) ? 8 : 0);   // A-trans: k row
    const int acolo = (g & 1) ? 8 : 0;         // A-trans: m col offset
    const int brow  = r + ((g & 1) ? 8 : 0);   // B-trans: k row
    const int bcolo = (g & 2) ? 8 : 0;         // B-trans: n col offset

    auto load_chunk = [&](int buf, int k0) {
        ScoresStage& s = stg[buf];
        {
            const size_t ro = base + (size_t)(k0 + lr0) * HW;
            cpasync16(&s.Ah[lr0][lc0], &g_khi[ro + pBase + lc0]);
            cpasync16(&s.Al[lr0][lc0], &g_klo[ro + pBase + lc0]);
            cpasync16(&s.Bh[lr0][lc0], &g_qhi[ro + qBase + lc0]);
            cpasync16(&s.Bl[lr0][lc0], &g_qlo[ro + qBase + lc0]);
        }
        {
            const size_t ro = base + (size_t)(k0 + lr1) * HW;
            cpasync16(&s.Ah[lr1][lc1], &g_khi[ro + pBase + lc1]);
            cpasync16(&s.Al[lr1][lc1], &g_klo[ro + pBase + lc1]);
            cpasync16(&s.Bh[lr1][lc1], &g_qhi[ro + qBase + lc1]);
            cpasync16(&s.Bl[lr1][lc1], &g_qlo[ro + qBase + lc1]);
        }
    };

    const int NCHUNK = CC / 32;   // 8
    load_chunk(0, 0);  cp_commit();
    load_chunk(1, 32); cp_commit();

    #pragma unroll 1
    for (int it = 0; it < NCHUNK; ++it) {
        cp_wait<1>();
        __syncthreads();
        if (it + 2 < NCHUNK) load_chunk((it + 2) % 3, (it + 2) * 32);
        cp_commit();

        ScoresStage& s = stg[it % 3];
        #pragma unroll
        for (int h = 0; h < 2; ++h) {
            uint32_t af[4][4], bfh[4][2], bfl[4][2];
            #pragma unroll
            for (int mt = 0; mt < 4; ++mt)
                ldsm4t(af[mt], smaddr(&s.Ah[h * 16 + arow][wm + mt * 16 + acolo]));
            #pragma unroll
            for (int np = 0; np < 2; ++np) {
                uint32_t t[4];
                ldsm4t(t, smaddr(&s.Bh[h * 16 + brow][wn + np * 16 + bcolo]));
                bfh[np*2][0] = t[0]; bfh[np*2][1] = t[1];
                bfh[np*2+1][0] = t[2]; bfh[np*2+1][1] = t[3];
            }
            #pragma unroll
            for (int mt = 0; mt < 4; ++mt)
                #pragma unroll
                for (int nn = 0; nn < 4; ++nn)
                    mma16816(acc[mt][nn], af[mt], bfh[nn]);

            #pragma unroll
            for (int np = 0; np < 2; ++np) {
                uint32_t t[4];
                ldsm4t(t, smaddr(&s.Bl[h * 16 + brow][wn + np * 16 + bcolo]));
                bfl[np*2][0] = t[0]; bfl[np*2][1] = t[1];
                bfl[np*2+1][0] = t[2]; bfl[np*2+1][1] = t[3];
            }
            #pragma unroll
            for (int mt = 0; mt < 4; ++mt)
                #pragma unroll
                for (int nn = 0; nn < 4; ++nn)
                    mma16816(acc[mt][nn], af[mt], bfl[nn]);

            #pragma unroll
            for (int mt = 0; mt < 4; ++mt)
                ldsm4t(af[mt], smaddr(&s.Al[h * 16 + arow][wm + mt * 16 + acolo]));
            #pragma unroll
            for (int mt = 0; mt < 4; ++mt)
                #pragma unroll
                for (int nn = 0; nn < 4; ++nn)
                    mma16816(acc[mt][nn], af[mt], bfh[nn]);
        }
    }

    // epilogue: e = exp(s/16); emit bf16 hi/lo; column partial sums
    const float sc = 1.0f / 16.0f;
    const size_t ebase = (size_t)nt * HW * HW;
    const int tr  = lane >> 2;
    const int tc2 = (lane & 3) * 2;
    float csum[4][2];
    #pragma unroll
    for (int nn = 0; nn < 4; ++nn) { csum[nn][0] = 0.f; csum[nn][1] = 0.f; }

    #pragma unroll
    for (int mt = 0; mt < 4; ++mt) {
        #pragma unroll
        for (int nn = 0; nn < 4; ++nn) {
            const int m = pBase + wm + mt * 16 + tr;
            const int n = qBase + wn + nn * 8 + tc2;
            float e00 = __expf(acc[mt][nn][0] * sc);
            float e01 = __expf(acc[mt][nn][1] * sc);
            float e10 = __expf(acc[mt][nn][2] * sc);
            float e11 = __expf(acc[mt][nn][3] * sc);
            __nv_bfloat16 h00 = __float2bfloat16(e00);
            __nv_bfloat16 h01 = __float2bfloat16(e01);
            __nv_bfloat16 h10 = __float2bfloat16(e10);
            __nv_bfloat16 h11 = __float2bfloat16(e11);
            __nv_bfloat162 hh0 = {h00, h01}, hh1 = {h10, h11};
            __nv_bfloat162 ll0 = {__float2bfloat16(e00 - __bfloat162float(h00)),
                                  __float2bfloat16(e01 - __bfloat162float(h01))};
            __nv_bfloat162 ll1 = {__float2bfloat16(e10 - __bfloat162float(h10)),
                                  __float2bfloat16(e11 - __bfloat162float(h11))};
            const size_t o0 = ebase + (size_t)m * HW + n;
            const size_t o1 = o0 + (size_t)8 * HW;
            *(__nv_bfloat162*)&g_ehi[o0] = hh0;
            *(__nv_bfloat162*)&g_elo[o0] = ll0;
            *(__nv_bfloat162*)&g_ehi[o1] = hh1;
            *(__nv_bfloat162*)&g_elo[o1] = ll1;
            csum[nn][0] += e00 + e10;
            csum[nn][1] += e01 + e11;
        }
    }
    // reduce over the 8 lanes sharing a column pair (tr bits = lane bits 2..4)
    #pragma unroll
    for (int nn = 0; nn < 4; ++nn) {
        #pragma unroll
        for (int j = 0; j < 2; ++j) {
            float v = csum[nn][j];
            v += __shfl_xor_sync(0xFFFFFFFF, v, 4);
            v += __shfl_xor_sync(0xFFFFFFFF, v, 8);
            v += __shfl_xor_sync(0xFFFFFFFF, v, 16);
            csum[nn][j] = v;
        }
    }
    if (lane < 4) {
        const int py2 = blockIdx.y * 2 + (warp & 1);
        const size_t pb = ((size_t)nt * 16 + py2) * HW;
        #pragma unroll
        for (int nn = 0; nn < 4; ++nn) {
            const int n = qBase + wn + nn * 8 + (lane & 3) * 2;
            g_partial[pb + n]     = csum[nn][0];
            g_partial[pb + n + 1] = csum[nn][1];
        }
    }
}

// ---------------------------------------------------------------------
// Kernel 2a: inv[nt][q] = 1 / sum over 16 partials
// ---------------------------------------------------------------------
__global__ __launch_bounds__(256) void inv_kernel()
{
    const int i = blockIdx.x * 256 + threadIdx.x;   // < NT*HW
    const int nt = i >> 10;
    const int q  = i & (HW - 1);
    float s = 0.f;
    #pragma unroll
    for (int j = 0; j < 16; ++j)
        s += g_partial[((size_t)nt * 16 + j) * HW + q];
    g_inv[i] = 1.0f / s;
}

// ---------------------------------------------------------------------
// Kernel 2b: attn[nt][p][q] = (e_hi + e_lo) * inv[nt][q]   (fp32 output)
// ---------------------------------------------------------------------
__global__ __launch_bounds__(256) void normalize_kernel(float* __restrict__ attn)
{
    const size_t i = (size_t)blockIdx.x * 256 + threadIdx.x;  // one float4 each
    const size_t idx = i * 4;
    const int q  = (int)(idx & (HW - 1));
    const int nt = (int)(idx >> 20);
    float4 iv = *(const float4*)&g_inv[nt * HW + q];
    __nv_bfloat162 h01 = *(const __nv_bfloat162*)&g_ehi[idx];
    __nv_bfloat162 h23 = *(const __nv_bfloat162*)&g_ehi[idx + 2];
    __nv_bfloat162 l01 = *(const __nv_bfloat162*)&g_elo[idx];
    __nv_bfloat162 l23 = *(const __nv_bfloat162*)&g_elo[idx + 2];
    float2 a = __bfloat1622float2(h01), b = __bfloat1622float2(l01);
    float2 c = __bfloat1622float2(h23), d = __bfloat1622float2(l23);
    float4 o;
    o.x = (a.x + b.x) * iv.x;
    o.y = (a.y + b.y) * iv.y;
    o.z = (c.x + d.x) * iv.z;
    o.w = (c.y + d.y) * iv.w;
    *(float4*)&attn[idx] = o;
}

// ---------------------------------------------------------------------
// Kernel 3: p_val[c][q] = inv[q] * sum_p V[c][p] * e[p][q]
// Tensor cores + split-bf16; BK=16, 4-stage cp.async pipeline.
// ---------------------------------------------------------------------
struct PvalStage {
    __nv_bfloat16 Vh[128][24], Vl[128][24], Th[16][136], Tl[16][136];
};

__global__ __launch_bounds__(256, 2) void pval_tc_kernel(float* __restrict__ O)
{
    extern __shared__ char dynsmem[];
    PvalStage* stg = reinterpret_cast<PvalStage*>(dynsmem);

    const int nt    = blockIdx.z;
    const int cBase = blockIdx.y * 128;
    const int qBase = blockIdx.x * 128;

    const int tid  = threadIdx.x;
    const int lane = tid & 31;
    const int warp = tid >> 5;
    const int wm   = (warp & 1) * 64;
    const int wn   = (warp >> 1) * 32;

    float acc[4][4][4];
    #pragma unroll
    for (int i = 0; i < 4; ++i)
        #pragma unroll
        for (int j = 0; j < 4; ++j)
            #pragma unroll
            for (int k = 0; k < 4; ++k) acc[i][j][k] = 0.f;

    const int vrow = tid >> 1;        // 0..127
    const int vcol = (tid & 1) * 8;   // 0 or 8
    const int trow = tid >> 4;        // 0..15
    const int tcol = (tid & 15) * 8;  // 0..120

    const size_t vbase = (size_t)nt * C2 * HW;
    const size_t ebase = (size_t)nt * HW * HW;

    const int g = lane >> 3, r = lane & 7;
    const int amro  = r + ((g & 1) ? 8 : 0);   // A non-trans row offset
    const int acolo = (g & 2) ? 8 : 0;
    const int brow  = r + ((g & 1) ? 8 : 0);   // B-trans
    const int bcolo = (g & 2) ? 8 : 0;

    auto load_chunk = [&](int buf, int k0) {
        PvalStage& s = stg[buf];
        const size_t vo = vbase + (size_t)(cBase + vrow) * HW + k0 + vcol;
        cpasync16(&s.Vh[vrow][vcol], &g_vhi[vo]);
        cpasync16(&s.Vl[vrow][vcol], &g_vlo[vo]);
        const size_t ao = ebase + (size_t)(k0 + trow) * HW + qBase + tcol;
        cpasync16(&s.Th[trow][tcol], &g_ehi[ao]);
        cpasync16(&s.Tl[trow][tcol], &g_elo[ao]);
    };

    const int NCHUNK = HW / 16;   // 64
    load_chunk(0, 0);  cp_commit();
    load_chunk(1, 16); cp_commit();
    load_chunk(2, 32); cp_commit();

    #pragma unroll 1
    for (int it = 0; it < NCHUNK; ++it) {
        cp_wait<2>();
        __syncthreads();
        if (it + 3 < NCHUNK) load_chunk((it + 3) & 3, (it + 3) * 16);
        cp_commit();

        PvalStage& s = stg[it & 3];
        uint32_t af[4][4], bfh[4][2], bfl[4][2];

        #pragma unroll
        for (int mt = 0; mt < 4; ++mt)
            ldsm4(af[mt], smaddr(&s.Vh[wm + mt * 16 + amro][acolo]));
        #pragma unroll
        for (int np = 0; np < 2; ++np) {
            uint32_t t[4];
            ldsm4t(t, smaddr(&s.Th[brow][wn + np * 16 + bcolo]));
            bfh[np*2][0] = t[0]; bfh[np*2][1] = t[1];
            bfh[np*2+1][0] = t[2]; bfh[np*2+1][1] = t[3];
        }
        #pragma unroll
        for (int mt = 0; mt < 4; ++mt)
            #pragma unroll
            for (int nn = 0; nn < 4; ++nn)
                mma16816(acc[mt][nn], af[mt], bfh[nn]);

        #pragma unroll
        for (int np = 0; np < 2; ++np) {
            uint32_t t[4];
            ldsm4t(t, smaddr(&s.Tl[brow][wn + np * 16 + bcolo]));
            bfl[np*2][0] = t[0]; bfl[np*2][1] = t[1];
            bfl[np*2+1][0] = t[2]; bfl[np*2+1][1] = t[3];
        }
        #pragma unroll
        for (int mt = 0; mt < 4; ++mt)
            #pragma unroll
            for (int nn = 0; nn < 4; ++nn)
                mma16816(acc[mt][nn], af[mt], bfl[nn]);

        #pragma unroll
        for (int mt = 0; mt < 4; ++mt)
            ldsm4(af[mt], smaddr(&s.Vl[wm + mt * 16 + amro][acolo]));
        #pragma unroll
        for (int mt = 0; mt < 4; ++mt)
            #pragma unroll
            for (int nn = 0; nn < 4; ++nn)
                mma16816(acc[mt][nn], af[mt], bfh[nn]);
    }

    float* Ob = O + (size_t)nt * C2 * HW;
    const float* inv = g_inv + nt * HW;
    const int tr  = lane >> 2;
    const int tc2 = (lane & 3) * 2;
    #pragma unroll
    for (int mt = 0; mt < 4; ++mt) {
        #pragma unroll
        for (int nn = 0; nn < 4; ++nn) {
            const int m = cBase + wm + mt * 16 + tr;
            const int n = qBase + wn + nn * 8 + tc2;
            const float i0 = inv[n], i1 = inv[n + 1];
            float2 v0 = {acc[mt][nn][0] * i0, acc[mt][nn][1] * i1};
            float2 v1 = {acc[mt][nn][2] * i0, acc[mt][nn][3] * i1};
            *(float2*)&Ob[(size_t)m * HW + n]       = v0;
            *(float2*)&Ob[(size_t)(m + 8) * HW + n] = v1;
        }
    }
}

// ---------------------------------------------------------------------
extern "C" void kernel_launch(void* const* d_in, const int* in_sizes, int n_in,
                              void* d_out, int out_size)
{
    const float* K = (const float*)d_in[0];   // key
    const float* Q = (const float*)d_in[1];   // query
    const float* V = (const float*)d_in[2];   // value

    float* out  = (float*)d_out;
    float* pval = out;                 // [nt][c2][q]
    float* attn = out + PVAL_ELEMS;    // [nt][p][q]

    const int scores_smem = (int)sizeof(ScoresStage) * 3;   // 104448
    const int pval_smem   = (int)sizeof(PvalStage) * 4;     // 83968
    static bool attr_done = false;
    // idempotent attribute config (host-side, not a stream op)
    cudaFuncSetAttribute(scores_tc_kernel, cudaFuncAttributeMaxDynamicSharedMemorySize, scores_smem);
    cudaFuncSetAttribute(pval_tc_kernel,   cudaFuncAttributeMaxDynamicSharedMemorySize, pval_smem);
    (void)attr_done;

    // 0) fp32 -> bf16 hi/lo splits (K, Q, V)
    {
        dim3 grid(512, 3);
        split_kernel<<<grid, 256>>>(K, Q, V);
    }
    // 1) e = exp(scores); bf16 hi/lo + column partial sums
    {
        dim3 grid(HW / 128, HW / 128, NT);
        scores_tc_kernel<<<grid, 256, scores_smem>>>();
    }
    // 2a) inverse column sums
    inv_kernel<<<(NT * HW) / 256, 256>>>();
    // 2b) attn = (hi+lo) * inv
    {
        const size_t nvec = (size_t)NT * HW * HW / 4;
        normalize_kernel<<<(unsigned)(nvec / 256), 256>>>(attn);
    }
    // 3) p_val = (V @ e) * inv
    {
        dim3 grid(HW / 128, C2 / 128, NT);
        pval_tc_kernel<<<grid, 256, pval_smem>>>(pval);
    }
}

// round 6
// speedup vs baseline: 2.5565x; 1.1172x over previous
#include <cuda_runtime.h>
#include <cuda_bf16.h>
#include <math_constants.h>
#include <cstdint>

// Shapes (fixed by the problem)
#define NB 4
#define TB 8
#define NT (NB*TB)        // 32 batches
#define CC 256            // channels (reduction dim for scores)
#define C2 256            // value channels
#define HW 1024           // p == q == H*W
#define PVAL_ELEMS ((size_t)NT * C2 * HW)
#define KQV_ELEMS (NT * CC * HW)

// ---- scratch (static __device__; no allocation) ----
__device__ __nv_bfloat16 g_khi[KQV_ELEMS];
__device__ __nv_bfloat16 g_klo[KQV_ELEMS];
__device__ __nv_bfloat16 g_qhi[KQV_ELEMS];
__device__ __nv_bfloat16 g_qlo[KQV_ELEMS];
__device__ __nv_bfloat16 g_vhi[KQV_ELEMS];
__device__ __nv_bfloat16 g_vlo[KQV_ELEMS];
__device__ __nv_bfloat16 g_ehi[(size_t)NT * HW * HW];   // exp(scores) hi
__device__ __nv_bfloat16 g_elo[(size_t)NT * HW * HW];   // exp(scores) lo
__device__ float g_partial[(size_t)NT * 16 * HW];       // per (ptile,mhalf) column sums
__device__ float g_inv[NT * HW];                        // 1 / column sum

// ---------------------------------------------------------------------
// helpers
// ---------------------------------------------------------------------
__device__ __forceinline__ unsigned smaddr(const void* p) {
    return (unsigned)__cvta_generic_to_shared(p);
}
__device__ __forceinline__ void ldsm4(uint32_t* d, unsigned a) {
    asm volatile("ldmatrix.sync.aligned.m8n8.x4.shared.b16 {%0,%1,%2,%3}, [%4];"
                 : "=r"(d[0]), "=r"(d[1]), "=r"(d[2]), "=r"(d[3]) : "r"(a));
}
__device__ __forceinline__ void ldsm4t(uint32_t* d, unsigned a) {
    asm volatile("ldmatrix.sync.aligned.m8n8.x4.trans.shared.b16 {%0,%1,%2,%3}, [%4];"
                 : "=r"(d[0]), "=r"(d[1]), "=r"(d[2]), "=r"(d[3]) : "r"(a));
}
__device__ __forceinline__ void mma16816(float* d, const uint32_t* a, const uint32_t* b) {
    asm volatile("mma.sync.aligned.m16n8k16.row.col.f32.bf16.bf16.f32 "
                 "{%0,%1,%2,%3}, {%4,%5,%6,%7}, {%8,%9}, {%0,%1,%2,%3};"
                 : "+f"(d[0]), "+f"(d[1]), "+f"(d[2]), "+f"(d[3])
                 : "r"(a[0]), "r"(a[1]), "r"(a[2]), "r"(a[3]), "r"(b[0]), "r"(b[1]));
}
__device__ __forceinline__ void cpasync16(void* dst, const void* src) {
    unsigned d = smaddr(dst);
    asm volatile("cp.async.cg.shared.global [%0], [%1], 16;" :: "r"(d), "l"(src));
}
__device__ __forceinline__ void cp_commit() {
    asm volatile("cp.async.commit_group;");
}
template <int N>
__device__ __forceinline__ void cp_wait() {
    asm volatile("cp.async.wait_group %0;" :: "n"(N));
}

// ---------------------------------------------------------------------
// Kernel 0: split fp32 -> (bf16 hi, bf16 lo) for K, Q, V.
// ---------------------------------------------------------------------
__global__ __launch_bounds__(256) void split_kernel(
    const float* __restrict__ K, const float* __restrict__ Q, const float* __restrict__ V)
{
    const float* src;
    __nv_bfloat16 *hi, *lo;
    if (blockIdx.y == 0)      { src = K; hi = g_khi; lo = g_klo; }
    else if (blockIdx.y == 1) { src = Q; hi = g_qhi; lo = g_qlo; }
    else                      { src = V; hi = g_vhi; lo = g_vlo; }

    int i = blockIdx.x * blockDim.x + threadIdx.x;
    int stride = gridDim.x * blockDim.x;
    for (; i < KQV_ELEMS / 4; i += stride) {
        float4 x = reinterpret_cast<const float4*>(src)[i];
        __nv_bfloat16 h0 = __float2bfloat16(x.x);
        __nv_bfloat16 h1 = __float2bfloat16(x.y);
        __nv_bfloat16 h2 = __float2bfloat16(x.z);
        __nv_bfloat16 h3 = __float2bfloat16(x.w);
        __nv_bfloat162 hh0 = {h0, h1}, hh1 = {h2, h3};
        __nv_bfloat162 ll0 = {__float2bfloat16(x.x - __bfloat162float(h0)),
                              __float2bfloat16(x.y - __bfloat162float(h1))};
        __nv_bfloat162 ll1 = {__float2bfloat16(x.z - __bfloat162float(h2)),
                              __float2bfloat16(x.w - __bfloat162float(h3))};
        reinterpret_cast<__nv_bfloat162*>(hi)[i * 2 + 0] = hh0;
        reinterpret_cast<__nv_bfloat162*>(hi)[i * 2 + 1] = hh1;
        reinterpret_cast<__nv_bfloat162*>(lo)[i * 2 + 0] = ll0;
        reinterpret_cast<__nv_bfloat162*>(lo)[i * 2 + 1] = ll1;
    }
}

// ---------------------------------------------------------------------
// Kernel 1: e[p][q] = exp( (1/16) * sum_c K[c][p]*Q[c][q] )
// 128 threads, 4 warps, warp tile 64x64 (2x2 grid), BK=32, 3-stage cp.async.
// Emits bf16 hi/lo of e and deterministic per-(ptile) column sums.
// ---------------------------------------------------------------------
struct ScoresStage {
    __nv_bfloat16 Ah[32][136], Al[32][136], Bh[32][136], Bl[32][136];
};

__global__ __launch_bounds__(128, 2) void scores_tc_kernel()
{
    extern __shared__ char dynsmem[];
    ScoresStage* stg = reinterpret_cast<ScoresStage*>(dynsmem);

    const int nt    = blockIdx.z;
    const int pBase = blockIdx.y * 128;
    const int qBase = blockIdx.x * 128;

    const int tid  = threadIdx.x;
    const int lane = tid & 31;
    const int warp = tid >> 5;
    const int wm   = (warp >> 1) * 64;
    const int wn   = (warp & 1) * 64;

    float acc[4][8][4];
    #pragma unroll
    for (int i = 0; i < 4; ++i)
        #pragma unroll
        for (int j = 0; j < 8; ++j)
            #pragma unroll
            for (int k = 0; k < 4; ++k) acc[i][j][k] = 0.f;

    const size_t base = (size_t)nt * CC * HW;

    // ldmatrix lane-group geometry
    const int g = lane >> 3, r = lane & 7;
    const int arow  = r + ((g & 2) ? 8 : 0);   // A-trans: k row
    const int acolo = (g & 1) ? 8 : 0;         // A-trans: m col offset
    const int brow  = r + ((g & 1) ? 8 : 0);   // B-trans: k row
    const int bcolo = (g & 2) ? 8 : 0;         // B-trans: n col offset

    auto load_chunk = [&](int buf, int k0) {
        ScoresStage& s = stg[buf];
        #pragma unroll
        for (int j = 0; j < 4; ++j) {
            const int v  = tid + j * 128;     // 0..511
            const int rr = v >> 4;
            const int cc = (v & 15) * 8;
            const size_t ro = base + (size_t)(k0 + rr) * HW;
            cpasync16(&s.Ah[rr][cc], &g_khi[ro + pBase + cc]);
            cpasync16(&s.Al[rr][cc], &g_klo[ro + pBase + cc]);
            cpasync16(&s.Bh[rr][cc], &g_qhi[ro + qBase + cc]);
            cpasync16(&s.Bl[rr][cc], &g_qlo[ro + qBase + cc]);
        }
    };

    const int NCHUNK = CC / 32;   // 8
    load_chunk(0, 0);  cp_commit();
    load_chunk(1, 32); cp_commit();

    #pragma unroll 1
    for (int it = 0; it < NCHUNK; ++it) {
        cp_wait<1>();
        __syncthreads();
        if (it + 2 < NCHUNK) load_chunk((it + 2) % 3, (it + 2) * 32);
        cp_commit();

        ScoresStage& s = stg[it % 3];
        #pragma unroll
        for (int h = 0; h < 2; ++h) {
            uint32_t afh[4][4], afl[4][4], bfh[8][2], bfl[8][2];
            #pragma unroll
            for (int mt = 0; mt < 4; ++mt)
                ldsm4t(afh[mt], smaddr(&s.Ah[h * 16 + arow][wm + mt * 16 + acolo]));
            #pragma unroll
            for (int np = 0; np < 4; ++np) {
                uint32_t t[4];
                ldsm4t(t, smaddr(&s.Bh[h * 16 + brow][wn + np * 16 + bcolo]));
                bfh[np*2][0] = t[0]; bfh[np*2][1] = t[1];
                bfh[np*2+1][0] = t[2]; bfh[np*2+1][1] = t[3];
            }
            #pragma unroll
            for (int mt = 0; mt < 4; ++mt)
                #pragma unroll
                for (int nn = 0; nn < 8; ++nn)
                    mma16816(acc[mt][nn], afh[mt], bfh[nn]);

            #pragma unroll
            for (int np = 0; np < 4; ++np) {
                uint32_t t[4];
                ldsm4t(t, smaddr(&s.Bl[h * 16 + brow][wn + np * 16 + bcolo]));
                bfl[np*2][0] = t[0]; bfl[np*2][1] = t[1];
                bfl[np*2+1][0] = t[2]; bfl[np*2+1][1] = t[3];
            }
            #pragma unroll
            for (int mt = 0; mt < 4; ++mt)
                #pragma unroll
                for (int nn = 0; nn < 8; ++nn)
                    mma16816(acc[mt][nn], afh[mt], bfl[nn]);

            #pragma unroll
            for (int mt = 0; mt < 4; ++mt)
                ldsm4t(afl[mt], smaddr(&s.Al[h * 16 + arow][wm + mt * 16 + acolo]));
            #pragma unroll
            for (int mt = 0; mt < 4; ++mt)
                #pragma unroll
                for (int nn = 0; nn < 8; ++nn)
                    mma16816(acc[mt][nn], afl[mt], bfh[nn]);
        }
    }

    // epilogue: e = exp(s/16); emit bf16 hi/lo; column partial sums
    const float sc = 1.0f / 16.0f;
    const size_t ebase = (size_t)nt * HW * HW;
    const int tr  = lane >> 2;
    const int tc2 = (lane & 3) * 2;
    float csum[8][2];
    #pragma unroll
    for (int nn = 0; nn < 8; ++nn) { csum[nn][0] = 0.f; csum[nn][1] = 0.f; }

    #pragma unroll
    for (int mt = 0; mt < 4; ++mt) {
        #pragma unroll
        for (int nn = 0; nn < 8; ++nn) {
            const int m = pBase + wm + mt * 16 + tr;
            const int n = qBase + wn + nn * 8 + tc2;
            float e00 = __expf(acc[mt][nn][0] * sc);
            float e01 = __expf(acc[mt][nn][1] * sc);
            float e10 = __expf(acc[mt][nn][2] * sc);
            float e11 = __expf(acc[mt][nn][3] * sc);
            __nv_bfloat16 h00 = __float2bfloat16(e00);
            __nv_bfloat16 h01 = __float2bfloat16(e01);
            __nv_bfloat16 h10 = __float2bfloat16(e10);
            __nv_bfloat16 h11 = __float2bfloat16(e11);
            __nv_bfloat162 hh0 = {h00, h01}, hh1 = {h10, h11};
            __nv_bfloat162 ll0 = {__float2bfloat16(e00 - __bfloat162float(h00)),
                                  __float2bfloat16(e01 - __bfloat162float(h01))};
            __nv_bfloat162 ll1 = {__float2bfloat16(e10 - __bfloat162float(h10)),
                                  __float2bfloat16(e11 - __bfloat162float(h11))};
            const size_t o0 = ebase + (size_t)m * HW + n;
            const size_t o1 = o0 + (size_t)8 * HW;
            *(__nv_bfloat162*)&g_ehi[o0] = hh0;
            *(__nv_bfloat162*)&g_elo[o0] = ll0;
            *(__nv_bfloat162*)&g_ehi[o1] = hh1;
            *(__nv_bfloat162*)&g_elo[o1] = ll1;
            csum[nn][0] += e00 + e10;
            csum[nn][1] += e01 + e11;
        }
    }
    // reduce over the 8 lanes sharing a column pair
    #pragma unroll
    for (int nn = 0; nn < 8; ++nn) {
        #pragma unroll
        for (int j = 0; j < 2; ++j) {
            float v = csum[nn][j];
            v += __shfl_xor_sync(0xFFFFFFFF, v, 4);
            v += __shfl_xor_sync(0xFFFFFFFF, v, 8);
            v += __shfl_xor_sync(0xFFFFFFFF, v, 16);
            csum[nn][j] = v;
        }
    }
    if (lane < 4) {
        const int py2 = blockIdx.y * 2 + (warp >> 1);
        const size_t pb = ((size_t)nt * 16 + py2) * HW;
        #pragma unroll
        for (int nn = 0; nn < 8; ++nn) {
            const int n = qBase + wn + nn * 8 + (lane & 3) * 2;
            g_partial[pb + n]     = csum[nn][0];
            g_partial[pb + n + 1] = csum[nn][1];
        }
    }
}

// ---------------------------------------------------------------------
// Kernel 2a: inv[nt][q] = 1 / sum over 16 partials
// ---------------------------------------------------------------------
__global__ __launch_bounds__(256) void inv_kernel()
{
    const int i = blockIdx.x * 256 + threadIdx.x;   // < NT*HW
    const int nt = i >> 10;
    const int q  = i & (HW - 1);
    float s = 0.f;
    #pragma unroll
    for (int j = 0; j < 16; ++j)
        s += g_partial[((size_t)nt * 16 + j) * HW + q];
    g_inv[i] = 1.0f / s;
}

// ---------------------------------------------------------------------
// Kernel 2b: attn[nt][p][q] = (e_hi + e_lo) * inv[nt][q]   (fp32 output)
// ---------------------------------------------------------------------
__global__ __launch_bounds__(256) void normalize_kernel(float* __restrict__ attn)
{
    const size_t i = (size_t)blockIdx.x * 256 + threadIdx.x;  // one float4 each
    const size_t idx = i * 4;
    const int q  = (int)(idx & (HW - 1));
    const int nt = (int)(idx >> 20);
    float4 iv = *(const float4*)&g_inv[nt * HW + q];
    __nv_bfloat162 h01 = *(const __nv_bfloat162*)&g_ehi[idx];
    __nv_bfloat162 h23 = *(const __nv_bfloat162*)&g_ehi[idx + 2];
    __nv_bfloat162 l01 = *(const __nv_bfloat162*)&g_elo[idx];
    __nv_bfloat162 l23 = *(const __nv_bfloat162*)&g_elo[idx + 2];
    float2 a = __bfloat1622float2(h01), b = __bfloat1622float2(l01);
    float2 c = __bfloat1622float2(h23), d = __bfloat1622float2(l23);
    float4 o;
    o.x = (a.x + b.x) * iv.x;
    o.y = (a.y + b.y) * iv.y;
    o.z = (c.x + d.x) * iv.z;
    o.w = (c.y + d.y) * iv.w;
    *(float4*)&attn[idx] = o;
}

// ---------------------------------------------------------------------
// Kernel 3: p_val[c][q] = inv[q] * sum_p V[c][p] * e[p][q]
// 128 threads, 4 warps, warp tile 64x64, BK=16, 4-stage cp.async.
// ---------------------------------------------------------------------
struct PvalStage {
    __nv_bfloat16 Vh[128][24], Vl[128][24], Th[16][136], Tl[16][136];
};

__global__ __launch_bounds__(128, 2) void pval_tc_kernel(float* __restrict__ O)
{
    extern __shared__ char dynsmem[];
    PvalStage* stg = reinterpret_cast<PvalStage*>(dynsmem);
    __shared__ float sinv[128];

    const int nt    = blockIdx.z;
    const int cBase = blockIdx.y * 128;
    const int qBase = blockIdx.x * 128;

    const int tid  = threadIdx.x;
    const int lane = tid & 31;
    const int warp = tid >> 5;
    const int wm   = (warp >> 1) * 64;
    const int wn   = (warp & 1) * 64;

    sinv[tid] = g_inv[nt * HW + qBase + tid];

    float acc[4][8][4];
    #pragma unroll
    for (int i = 0; i < 4; ++i)
        #pragma unroll
        for (int j = 0; j < 8; ++j)
            #pragma unroll
            for (int k = 0; k < 4; ++k) acc[i][j][k] = 0.f;

    const size_t vbase = (size_t)nt * C2 * HW;
    const size_t ebase = (size_t)nt * HW * HW;

    const int g = lane >> 3, r = lane & 7;
    const int amro  = r + ((g & 1) ? 8 : 0);   // A non-trans row offset
    const int acolo = (g & 2) ? 8 : 0;
    const int brow  = r + ((g & 1) ? 8 : 0);   // B-trans
    const int bcolo = (g & 2) ? 8 : 0;

    auto load_chunk = [&](int buf, int k0) {
        PvalStage& s = stg[buf];
        #pragma unroll
        for (int j = 0; j < 2; ++j) {
            const int v  = tid + j * 128;        // 0..255
            const int vr = v >> 1;
            const int vc = (v & 1) * 8;
            const size_t vo = vbase + (size_t)(cBase + vr) * HW + k0 + vc;
            cpasync16(&s.Vh[vr][vc], &g_vhi[vo]);
            cpasync16(&s.Vl[vr][vc], &g_vlo[vo]);
            const int trr = v >> 4;
            const int tcc = (v & 15) * 8;
            const size_t ao = ebase + (size_t)(k0 + trr) * HW + qBase + tcc;
            cpasync16(&s.Th[trr][tcc], &g_ehi[ao]);
            cpasync16(&s.Tl[trr][tcc], &g_elo[ao]);
        }
    };

    const int NCHUNK = HW / 16;   // 64
    load_chunk(0, 0);  cp_commit();
    load_chunk(1, 16); cp_commit();
    load_chunk(2, 32); cp_commit();

    #pragma unroll 1
    for (int it = 0; it < NCHUNK; ++it) {
        cp_wait<2>();
        __syncthreads();
        if (it + 3 < NCHUNK) load_chunk((it + 3) & 3, (it + 3) * 16);
        cp_commit();

        PvalStage& s = stg[it & 3];
        uint32_t afh[4][4], afl[4][4], bfh[8][2], bfl[8][2];

        #pragma unroll
        for (int mt = 0; mt < 4; ++mt)
            ldsm4(afh[mt], smaddr(&s.Vh[wm + mt * 16 + amro][acolo]));
        #pragma unroll
        for (int np = 0; np < 4; ++np) {
            uint32_t t[4];
            ldsm4t(t, smaddr(&s.Th[brow][wn + np * 16 + bcolo]));
            bfh[np*2][0] = t[0]; bfh[np*2][1] = t[1];
            bfh[np*2+1][0] = t[2]; bfh[np*2+1][1] = t[3];
        }
        #pragma unroll
        for (int mt = 0; mt < 4; ++mt)
            #pragma unroll
            for (int nn = 0; nn < 8; ++nn)
                mma16816(acc[mt][nn], afh[mt], bfh[nn]);

        #pragma unroll
        for (int np = 0; np < 4; ++np) {
            uint32_t t[4];
            ldsm4t(t, smaddr(&s.Tl[brow][wn + np * 16 + bcolo]));
            bfl[np*2][0] = t[0]; bfl[np*2][1] = t[1];
            bfl[np*2+1][0] = t[2]; bfl[np*2+1][1] = t[3];
        }
        #pragma unroll
        for (int mt = 0; mt < 4; ++mt)
            #pragma unroll
            for (int nn = 0; nn < 8; ++nn)
                mma16816(acc[mt][nn], afh[mt], bfl[nn]);

        #pragma unroll
        for (int mt = 0; mt < 4; ++mt)
            ldsm4(afl[mt], smaddr(&s.Vl[wm + mt * 16 + amro][acolo]));
        #pragma unroll
        for (int mt = 0; mt < 4; ++mt)
            #pragma unroll
            for (int nn = 0; nn < 8; ++nn)
                mma16816(acc[mt][nn], afl[mt], bfh[nn]);
    }

    float* Ob = O + (size_t)nt * C2 * HW;
    const int tr  = lane >> 2;
    const int tc2 = (lane & 3) * 2;
    #pragma unroll
    for (int mt = 0; mt < 4; ++mt) {
        #pragma unroll
        for (int nn = 0; nn < 8; ++nn) {
            const int m  = cBase + wm + mt * 16 + tr;
            const int nl = wn + nn * 8 + tc2;
            const int n  = qBase + nl;
            const float i0 = sinv[nl], i1 = sinv[nl + 1];
            float2 v0 = {acc[mt][nn][0] * i0, acc[mt][nn][1] * i1};
            float2 v1 = {acc[mt][nn][2] * i0, acc[mt][nn][3] * i1};
            *(float2*)&Ob[(size_t)m * HW + n]       = v0;
            *(float2*)&Ob[(size_t)(m + 8) * HW + n] = v1;
        }
    }
}

// ---------------------------------------------------------------------
extern "C" void kernel_launch(void* const* d_in, const int* in_sizes, int n_in,
                              void* d_out, int out_size)
{
    const float* K = (const float*)d_in[0];
    const float* Q = (const float*)d_in[1];
    const float* V = (const float*)d_in[2];

    float* out  = (float*)d_out;
    float* pval = out;                 // [nt][c2][q]
    float* attn = out + PVAL_ELEMS;    // [nt][p][q]

    const int scores_smem = (int)sizeof(ScoresStage) * 3;   // 104448
    const int pval_smem   = (int)sizeof(PvalStage) * 4;     // 83968
    cudaFuncSetAttribute(scores_tc_kernel, cudaFuncAttributeMaxDynamicSharedMemorySize, scores_smem);
    cudaFuncSetAttribute(pval_tc_kernel,   cudaFuncAttributeMaxDynamicSharedMemorySize, pval_smem);

    // 0) fp32 -> bf16 hi/lo splits (K, Q, V)
    {
        dim3 grid(512, 3);
        split_kernel<<<grid, 256>>>(K, Q, V);
    }
    // 1) e = exp(scores); bf16 hi/lo + column partial sums
    {
        dim3 grid(HW / 128, HW / 128, NT);
        scores_tc_kernel<<<grid, 128, scores_smem>>>();
    }
    // 2a) inverse column sums
    inv_kernel<<<(NT * HW) / 256, 256>>>();
    // 2b) attn = (hi+lo) * inv
    {
        const size_t nvec = (size_t)NT * HW * HW / 4;
        normalize_kernel<<<(unsigned)(nvec / 256), 256>>>(attn);
    }
    // 3) p_val = (V @ e) * inv
    {
        dim3 grid(HW / 128, C2 / 128, NT);
        pval_tc_kernel<<<grid, 128, pval_smem>>>(pval);
    }
}